// round 6
// baseline (speedup 1.0000x reference)
#include <cuda_runtime.h>
#include <math.h>
#include <stdint.h>

// ---------------- static problem config ----------------
#define BB 32
#define TT 12
#define NNODE 500
#define NSKIPC 256
#define NENDC 512
#define NPREDC 12
#define LL 8
#define RFh 13
#define BN_EPS 1e-5f

typedef unsigned long long ull;
typedef unsigned int u32;

__device__ __forceinline__ ull pack2(float lo, float hi) {
    ull r; asm("mov.b64 %0,{%1,%2};" : "=l"(r) : "f"(lo), "f"(hi)); return r;
}
__device__ __forceinline__ ull fma2(ull a, ull b, ull c) {
    ull d; asm("fma.rn.f32x2 %0,%1,%2,%3;" : "=l"(d) : "l"(a), "l"(b), "l"(c)); return d;
}
__device__ __forceinline__ void unpack2(ull v, float& lo, float& hi) {
    asm("mov.b64 {%0,%1},%2;" : "=f"(lo), "=f"(hi) : "l"(v));
}
__device__ __forceinline__ float to_tf32(float x) {
    u32 r; asm("cvt.rna.tf32.f32 %0, %1;" : "=r"(r) : "f"(x));
    return __uint_as_float(r);
}
__device__ __forceinline__ void mma_tf32(float* c, const u32* a, const u32* b) {
    asm("mma.sync.aligned.m16n8k8.row.col.f32.tf32.tf32.f32 "
        "{%0,%1,%2,%3},{%4,%5,%6,%7},{%8,%9},{%0,%1,%2,%3};"
        : "+f"(c[0]), "+f"(c[1]), "+f"(c[2]), "+f"(c[3])
        : "r"(a[0]), "r"(a[1]), "r"(a[2]), "r"(a[3]), "r"(b[0]), "r"(b[1]));
}

// ---------------- device scratch ----------------
__device__ float g_P[NNODE * 64];
__device__ float g_Q[NNODE * 64];
__device__ float g_eraw[2 * NNODE * NNODE];
__device__ float g_Scat[NNODE * 2000];            // [v][ A0 | A0^2 | A1 | A1^2 ]
__device__ float g_tmp[BB * TT * 32 * 2];
__device__ float g_X0[BB * 32 * RFh * NNODE];
__device__ float g_X1[BB * 32 * RFh * NNODE];
__device__ float g_XG[BB * 32 * 12 * NNODE];
__device__ float g_Y[12288 * 2000];               // diffusion outputs; reused as head hidden H
__device__ float g_XGcat[BB * 256 * NNODE];       // last-t gated slices, rows (l*32+c)
__device__ float g_Wcat[256 * 256];               // skip weights re-laid [o][l*32+c]
__device__ float g_skip[BB * NSKIPC * NNODE];
__device__ float g_Srelu[BB * NNODE * NSKIPC];
__device__ float g_o1wT[NSKIPC * NENDC];
__device__ float g_part[1536 * 64];               // per-block BN partial sums
__device__ float g_bnab[(LL + 1) * 64];           // per-layer fused BN scale/shift; slot LL = identity

// ---------------- fused one-time prep ----------------
__global__ void k_prep(const float* __restrict__ skp_w, const float* __restrict__ o1w) {
    int idx = blockIdx.x * 256 + threadIdx.x;
    if (idx < 64) g_bnab[LL * 64 + idx] = (idx < 32) ? 1.f : 0.f;
    if (idx < 65536) {
        int o = idx >> 8, r = idx & 255, l = r >> 5, c = r & 31;
        g_Wcat[idx] = skp_w[l * 8192 + o * 32 + c];
    }
    if (idx < 131072) {
        int h = idx / NSKIPC, c = idx % NSKIPC;
        g_o1wT[c * NENDC + h] = o1w[idx];
    }
}

// ---------------- adjacency ----------------
__global__ void k_pq(const float* __restrict__ factor, const float* __restrict__ map_w,
                     const float* __restrict__ map_b,
                     const float* __restrict__ a1w, const float* __restrict__ a1b) {
    __shared__ float vv[32];
    int j = blockIdx.x, h = threadIdx.x;   // 64 threads
    if (h < 32) {
        float acc = map_b[h];
#pragma unroll
        for (int u = 0; u < 32; u++) acc += factor[j * 32 + u] * map_w[u * 32 + h];
        vv[h] = fmaxf(acc, 0.f);
    }
    __syncthreads();
    float p = 0.f, q = a1b[h];
#pragma unroll
    for (int d = 0; d < 32; d++) {
        p += vv[d] * a1w[d * 64 + h];
        q += vv[d] * a1w[(32 + d) * 64 + h];
    }
    g_P[j * 64 + h] = p;
    g_Q[j * 64 + h] = q;
}

__global__ void k_adjmlp(const float* __restrict__ a2w, const float* __restrict__ a2b,
                         const float* __restrict__ a3w, const float* __restrict__ a3b) {
    __shared__ float Pt[128][65];
    __shared__ __align__(16) float sA2[64][32];
    __shared__ float sQ[64];
    __shared__ float sA3[64];
    __shared__ float sA2b[32];
    __shared__ float sA3b[2];
    int i = blockIdx.x, tid = threadIdx.x;
    for (int k = tid; k < 64 * 32; k += 128) sA2[k / 32][k % 32] = a2w[k];
    if (tid < 64) { sQ[tid] = g_Q[i * 64 + tid]; sA3[tid] = a3w[tid]; }
    if (tid < 32) sA2b[tid] = a2b[tid];
    if (tid < 2) sA3b[tid] = a3b[tid];
    for (int j0 = 0; j0 < NNODE; j0 += 128) {
        __syncthreads();
        int cnt = min(128, NNODE - j0);
        for (int k = tid; k < cnt * 64; k += 128)
            Pt[k / 64][k % 64] = g_P[(j0 + (k / 64)) * 64 + (k % 64)];
        __syncthreads();
        if (tid < cnt) {
            int j = j0 + tid;
            float h1[64];
#pragma unroll
            for (int h = 0; h < 64; h++) h1[h] = fmaxf(Pt[tid][h] + sQ[h], 0.f);
            float e0 = sA3b[0], e1 = sA3b[1];
#pragma unroll
            for (int c = 0; c < 32; c++) {
                float acc = sA2b[c];
#pragma unroll
                for (int h = 0; h < 64; h++) acc += h1[h] * sA2[h][c];
                acc = fmaxf(acc, 0.f);
                e0 += acc * sA3[c * 2];
                e1 += acc * sA3[c * 2 + 1];
            }
            g_eraw[i * NNODE + j] = e0;
            g_eraw[NNODE * NNODE + i * NNODE + j] = e1;
        }
    }
}

__global__ void k_softmax(float* __restrict__ outSup, int writeSup) {
    int bid = blockIdx.x;
    int e = bid / NNODE, i = bid % NNODE;
    const float* row = g_eraw + e * NNODE * NNODE + i * NNODE;
    __shared__ float red[256];
    int tid = threadIdx.x;
    float m = -1e30f;
    for (int j = tid; j < NNODE; j += 256) m = fmaxf(m, row[j]);
    red[tid] = m; __syncthreads();
    for (int s = 128; s > 0; s >>= 1) { if (tid < s) red[tid] = fmaxf(red[tid], red[tid + s]); __syncthreads(); }
    m = red[0]; __syncthreads();
    float sum = 0.f;
    for (int j = tid; j < NNODE; j += 256) sum += expf(row[j] - m);
    red[tid] = sum; __syncthreads();
    for (int s = 128; s > 0; s >>= 1) { if (tid < s) red[tid] += red[tid + s]; __syncthreads(); }
    float inv = 1.f / red[0];
    for (int j = tid; j < NNODE; j += 256) {
        float p = expf(row[j] - m) * inv;
        if (j == i) p = fmaxf(p, 1.f);
        g_Scat[i * 2000 + e * 1000 + j] = p;
        if (writeSup) outSup[(e * NNODE + i) * NNODE + j] = p;
    }
}

// ---------------- tf32 tensor GEMM v2: paired SMEM layouts (LDS.64 frags), 1 sync/kt ----------------
__global__ __launch_bounds__(256)
void tgemm(const float* __restrict__ A, const float* __restrict__ B, float* __restrict__ C,
           int M, int N, int K, int lda, int ldb, int ldc,
           int sA, int sB, int sC) {
    __shared__ __align__(16) float As[2][16][136];   // [buf][k][pcol(m)]
    __shared__ __align__(16) float Bs[2][128][18];   // [buf][n][pk(k)]
    A += (size_t)blockIdx.z * sA;
    B += (size_t)blockIdx.z * sB;
    C += (size_t)blockIdx.z * sC;
    int tid = threadIdx.x;
    int m0 = blockIdx.y * 128, n0 = blockIdx.x * 128;
    int lane = tid & 31, wid = tid >> 5;
    int wm = wid & 1, wn = wid >> 1;
    int gid = lane >> 2, tig = lane & 3;
    // loader indices
    int lm = tid >> 1, lrh = tid & 1;
    int pcolA = (lm & ~15) + ((lm & 7) << 1) + ((lm >> 3) & 1);
    int lkl = tid >> 4, lnq = (tid & 15) << 3;
    int pkB = (lkl & 8) + ((lkl & 3) << 1) + ((lkl >> 2) & 1);

    float acc[4][4][4];
#pragma unroll
    for (int mi = 0; mi < 4; mi++)
#pragma unroll
        for (int ni = 0; ni < 4; ni++)
#pragma unroll
            for (int r = 0; r < 4; r++) acc[mi][ni][r] = 0.f;

    int nkt = (K + 15) / 16;

    // ---- prologue: stage chunk 0 into buf 0 ----
    {
        float av[8], bv[8];
        int row = m0 + lm, c0 = lrh * 8;
        if (row < M && c0 + 7 < K) {
            float4 p = *(const float4*)(A + (size_t)row * lda + c0);
            float4 q = *(const float4*)(A + (size_t)row * lda + c0 + 4);
            av[0]=p.x; av[1]=p.y; av[2]=p.z; av[3]=p.w; av[4]=q.x; av[5]=q.y; av[6]=q.z; av[7]=q.w;
        } else {
#pragma unroll
            for (int l = 0; l < 8; l++)
                av[l] = (row < M && c0 + l < K) ? A[(size_t)row * lda + c0 + l] : 0.f;
        }
        int br = lkl, bc = n0 + lnq;
        if (br < K && bc + 7 < N) {
            float4 p = *(const float4*)(B + (size_t)br * ldb + bc);
            float4 q = *(const float4*)(B + (size_t)br * ldb + bc + 4);
            bv[0]=p.x; bv[1]=p.y; bv[2]=p.z; bv[3]=p.w; bv[4]=q.x; bv[5]=q.y; bv[6]=q.z; bv[7]=q.w;
        } else {
#pragma unroll
            for (int l = 0; l < 8; l++)
                bv[l] = (br < K && bc + l < N) ? B[(size_t)br * ldb + bc + l] : 0.f;
        }
#pragma unroll
        for (int l = 0; l < 8; l++) As[0][lrh * 8 + l][pcolA] = to_tf32(av[l]);
#pragma unroll
        for (int l = 0; l < 8; l++) Bs[0][lnq + l][pkB] = to_tf32(bv[l]);
    }
    __syncthreads();

    for (int kt = 0; kt < nkt; kt++) {
        int cur = kt & 1;
        bool hn = (kt + 1 < nkt);
        float av[8], bv[8];
        if (hn) {
            int kc0 = (kt + 1) * 16;
            int row = m0 + lm, c0 = kc0 + lrh * 8;
            if (row < M && c0 + 7 < K) {
                float4 p = *(const float4*)(A + (size_t)row * lda + c0);
                float4 q = *(const float4*)(A + (size_t)row * lda + c0 + 4);
                av[0]=p.x; av[1]=p.y; av[2]=p.z; av[3]=p.w; av[4]=q.x; av[5]=q.y; av[6]=q.z; av[7]=q.w;
            } else {
#pragma unroll
                for (int l = 0; l < 8; l++)
                    av[l] = (row < M && c0 + l < K) ? A[(size_t)row * lda + c0 + l] : 0.f;
            }
            int br = kc0 + lkl, bc = n0 + lnq;
            if (br < K && bc + 7 < N) {
                float4 p = *(const float4*)(B + (size_t)br * ldb + bc);
                float4 q = *(const float4*)(B + (size_t)br * ldb + bc + 4);
                bv[0]=p.x; bv[1]=p.y; bv[2]=p.z; bv[3]=p.w; bv[4]=q.x; bv[5]=q.y; bv[6]=q.z; bv[7]=q.w;
            } else {
#pragma unroll
                for (int l = 0; l < 8; l++)
                    bv[l] = (br < K && bc + l < N) ? B[(size_t)br * ldb + bc + l] : 0.f;
            }
        }
        // compute on cur: per ks-half, 12 LDS.64 + 16 mma
#pragma unroll
        for (int ks = 0; ks < 16; ks += 8) {
            ull a01[4], a23[4], b01[4];
            const float* Ak0 = &As[cur][ks + tig][wm * 64 + (gid << 1)];
            const float* Ak1 = &As[cur][ks + tig + 4][wm * 64 + (gid << 1)];
#pragma unroll
            for (int mi = 0; mi < 4; mi++) {
                a01[mi] = *(const ull*)(Ak0 + mi * 16);
                a23[mi] = *(const ull*)(Ak1 + mi * 16);
            }
#pragma unroll
            for (int ni = 0; ni < 4; ni++)
                b01[ni] = *(const ull*)&Bs[cur][wn * 32 + ni * 8 + gid][ks + (tig << 1)];
#pragma unroll
            for (int mi = 0; mi < 4; mi++) {
                u32 af[4] = {(u32)a01[mi], (u32)(a01[mi] >> 32),
                             (u32)a23[mi], (u32)(a23[mi] >> 32)};
#pragma unroll
                for (int ni = 0; ni < 4; ni++) {
                    u32 bf[2] = {(u32)b01[ni], (u32)(b01[ni] >> 32)};
                    mma_tf32(acc[mi][ni], af, bf);
                }
            }
        }
        if (hn) {
            int nxt = cur ^ 1;
#pragma unroll
            for (int l = 0; l < 8; l++) As[nxt][lrh * 8 + l][pcolA] = to_tf32(av[l]);
#pragma unroll
            for (int l = 0; l < 8; l++) Bs[nxt][lnq + l][pkB] = to_tf32(bv[l]);
            __syncthreads();
        }
    }
#pragma unroll
    for (int mi = 0; mi < 4; mi++) {
        int r0 = m0 + wm * 64 + mi * 16 + gid;
        int r1 = r0 + 8;
#pragma unroll
        for (int ni = 0; ni < 4; ni++) {
            int cc = n0 + wn * 32 + ni * 8 + tig * 2;
            if (r0 < M) {
                if (cc + 1 < N) *(float2*)(C + (size_t)r0 * ldc + cc) = make_float2(acc[mi][ni][0], acc[mi][ni][1]);
                else if (cc < N) C[(size_t)r0 * ldc + cc] = acc[mi][ni][0];
            }
            if (r1 < M) {
                if (cc + 1 < N) *(float2*)(C + (size_t)r1 * ldc + cc) = make_float2(acc[mi][ni][2], acc[mi][ni][3]);
                else if (cc < N) C[(size_t)r1 * ldc + cc] = acc[mi][ni][2];
            }
        }
    }
}

// ---------------- input split + enter ----------------
__global__ void k_tmp(const float* __restrict__ inputs, const float* __restrict__ factor) {
    int t = blockIdx.x, b = blockIdx.y, tid = threadIdx.x;
    int o = tid >> 2, r = tid & 3;
    int u = o >> 1, f = o & 1;
    const float* inp = inputs + ((size_t)(b * TT + t) * NNODE) * 2 + f;
    float acc = 0.f;
    for (int n = r; n < NNODE; n += 4) acc += inp[n * 2] * factor[n * 32 + u];
    acc += __shfl_down_sync(0xffffffffu, acc, 2);
    acc += __shfl_down_sync(0xffffffffu, acc, 1);
    if (r == 0) g_tmp[(b * TT + t) * 64 + o] = acc;
}

__global__ void k_enter(const float* __restrict__ inputs, const float* __restrict__ factor,
                        const float* __restrict__ ew, const float* __restrict__ eb,
                        float* __restrict__ X0) {
    __shared__ float sw[128], sb[32], stmp[64];
    int b = blockIdx.z, tp = blockIdx.y;
    int tid = threadIdx.x;
    if (tid < 128) sw[tid] = ew[tid];
    if (tid < 32) sb[tid] = eb[tid];
    if (tp > 0 && tid < 64) stmp[tid] = g_tmp[(b * TT + (tp - 1)) * 64 + tid];
    __syncthreads();
    int n = blockIdx.x * 128 + tid;
    if (n >= NNODE) return;
    if (tp == 0) {
#pragma unroll
        for (int o = 0; o < 32; o++)
            X0[((size_t)(b * 32 + o) * RFh + 0) * NNODE + n] = sb[o];
    } else {
        int t = tp - 1;
        float s0 = 0.f, s1 = 0.f;
#pragma unroll
        for (int u = 0; u < 32; u++) {
            float fv = factor[n * 32 + u];
            s0 += fv * stmp[u * 2];
            s1 += fv * stmp[u * 2 + 1];
        }
        float i0 = inputs[((size_t)(b * TT + t) * NNODE + n) * 2 + 0];
        float i1 = inputs[((size_t)(b * TT + t) * NNODE + n) * 2 + 1];
        float r0 = i0 - s0, r1 = i1 - s1;
#pragma unroll
        for (int o = 0; o < 32; o++) {
            float v = sb[o] + sw[o * 4] * s0 + sw[o * 4 + 1] * s1 + sw[o * 4 + 2] * r0 + sw[o * 4 + 3] * r1;
            X0[((size_t)(b * 32 + o) * RFh + tp) * NNODE + n] = v;
        }
    }
}

// ---------------- gated dilated temporal conv; BN affine fused on input ----------------
__global__ void k_gatefilter(const float* __restrict__ X, float* __restrict__ XG,
                             float* __restrict__ XGcat,
                             const float* __restrict__ fw, const float* __restrict__ fb,
                             const float* __restrict__ gw, const float* __restrict__ gb,
                             const float* __restrict__ abPrev,
                             int Tin, int Tout, int dd, int layer) {
    __shared__ __align__(16) float swf[2048];
    __shared__ __align__(16) float swg[2048];
    __shared__ float sfb[32], sgb[32], sA[32], sB[32];
    int tid = threadIdx.x;
    for (int idx = tid; idx < 2048; idx += 128) {
        int c = idx >> 6, r = idx & 63, kk = r >> 5, o = r & 31;
        swf[idx] = fw[(o << 6) + (c << 1) + kk];
        swg[idx] = gw[(o << 6) + (c << 1) + kk];
    }
    if (tid < 32) {
        sfb[tid] = fb[tid]; sgb[tid] = gb[tid];
        sA[tid] = abPrev[tid]; sB[tid] = abPrev[32 + tid];
    }
    __syncthreads();
    int n = blockIdx.x * 128 + tid;
    if (n >= NNODE) return;
    int t = blockIdx.y, b = blockIdx.z;
    ull fa2[16], ga2[16];
#pragma unroll
    for (int p = 0; p < 16; p++) {
        fa2[p] = pack2(sfb[p * 2], sfb[p * 2 + 1]);
        ga2[p] = pack2(sgb[p * 2], sgb[p * 2 + 1]);
    }
    const float* Xb = X + (size_t)(b * 32) * Tin * NNODE + n;
    for (int c = 0; c < 32; c++) {
        float xa = Xb[(size_t)(c * Tin + t) * NNODE] * sA[c] + sB[c];
        float xb = Xb[(size_t)(c * Tin + t + dd) * NNODE] * sA[c] + sB[c];
        ull xad = pack2(xa, xa), xbd = pack2(xb, xb);
        const ulonglong2* wf0 = (const ulonglong2*)&swf[c * 64];
        const ulonglong2* wf1 = (const ulonglong2*)&swf[c * 64 + 32];
        const ulonglong2* wg0 = (const ulonglong2*)&swg[c * 64];
        const ulonglong2* wg1 = (const ulonglong2*)&swg[c * 64 + 32];
#pragma unroll
        for (int p = 0; p < 8; p++) {
            ulonglong2 wa = wf0[p];
            fa2[p * 2 + 0] = fma2(xad, wa.x, fa2[p * 2 + 0]);
            fa2[p * 2 + 1] = fma2(xad, wa.y, fa2[p * 2 + 1]);
            ulonglong2 wb = wf1[p];
            fa2[p * 2 + 0] = fma2(xbd, wb.x, fa2[p * 2 + 0]);
            fa2[p * 2 + 1] = fma2(xbd, wb.y, fa2[p * 2 + 1]);
            ulonglong2 wc = wg0[p];
            ga2[p * 2 + 0] = fma2(xad, wc.x, ga2[p * 2 + 0]);
            ga2[p * 2 + 1] = fma2(xad, wc.y, ga2[p * 2 + 1]);
            ulonglong2 wd = wg1[p];
            ga2[p * 2 + 0] = fma2(xbd, wd.x, ga2[p * 2 + 0]);
            ga2[p * 2 + 1] = fma2(xbd, wd.y, ga2[p * 2 + 1]);
        }
    }
    bool last = (t == Tout - 1);
#pragma unroll
    for (int p = 0; p < 16; p++) {
        float f0, f1, g0, g1;
        unpack2(fa2[p], f0, f1);
        unpack2(ga2[p], g0, g1);
        float s0 = 1.f / (1.f + expf(-g0));
        float s1 = 1.f / (1.f + expf(-g1));
        float v0 = tanhf(f0) * s0, v1 = tanhf(f1) * s1;
        XG[((size_t)(b * 32 + p * 2 + 0) * Tout + t) * NNODE + n] = v0;
        XG[((size_t)(b * 32 + p * 2 + 1) * Tout + t) * NNODE + n] = v1;
        if (last) {
            XGcat[((size_t)b * 256 + layer * 32 + p * 2 + 0) * NNODE + n] = v0;
            XGcat[((size_t)b * 256 + layer * 32 + p * 2 + 1) * NNODE + n] = v1;
        }
    }
}

// ---------------- gc 1x1 + residual(BN-fused) + BN partial stats; adjacent node pairs ----------------
__global__ void k_gcres(const float* __restrict__ XG, const float* __restrict__ Y,
                        const float* __restrict__ Xc, float* __restrict__ Xn,
                        const float* __restrict__ gcw, const float* __restrict__ gcb,
                        const float* __restrict__ abPrev,
                        float* __restrict__ part, int Tin, int Tout, int dd) {
    __shared__ __align__(16) float swg[160 * 32];
    __shared__ float sgb[32], sA[32], sB[32];
    __shared__ float sredS[4][32];
    __shared__ float sredQ[4][32];
    int tid = threadIdx.x;
    for (int idx = tid; idx < 160 * 32; idx += 128) {
        int c = idx / 32, o = idx % 32;
        swg[idx] = gcw[o * 160 + c];
    }
    if (tid < 32) { sgb[tid] = gcb[tid]; sA[tid] = abPrev[tid]; sB[tid] = abPrev[32 + tid]; }
    __syncthreads();
    int n0 = blockIdx.x * 256 + tid * 2;      // adjacent pair (n0, n0+1); NNODE even
    int t = blockIdx.y, b = blockIdx.z;
    bool active = (n0 < NNODE);
    ull acc0[16], acc1[16];
#pragma unroll
    for (int q = 0; q < 16; q++) {
        ull bias = active ? pack2(sgb[q * 2], sgb[q * 2 + 1]) : pack2(0.f, 0.f);
        acc0[q] = bias;
        acc1[q] = bias;
    }
    for (int c = 0; c < 32; c++) {
        size_t base = ((size_t)(b * 32 + c) * Tout + t) * NNODE;
        float2 v = active ? *(const float2*)&XG[base + n0] : make_float2(0.f, 0.f);
        ull vd0 = pack2(v.x, v.x), vd1 = pack2(v.y, v.y);
        const ulonglong2* w2 = (const ulonglong2*)&swg[c * 32];
#pragma unroll
        for (int q = 0; q < 8; q++) {
            ulonglong2 w = w2[q];
            acc0[q * 2 + 0] = fma2(vd0, w.x, acc0[q * 2 + 0]);
            acc0[q * 2 + 1] = fma2(vd0, w.y, acc0[q * 2 + 1]);
            acc1[q * 2 + 0] = fma2(vd1, w.x, acc1[q * 2 + 0]);
            acc1[q * 2 + 1] = fma2(vd1, w.y, acc1[q * 2 + 1]);
        }
    }
    for (int e = 0; e < 4; e++) {
        for (int c = 0; c < 32; c++) {
            size_t m = ((size_t)(b * 32 + c) * Tout + t) * 2000 + e * 500;
            float2 v = active ? *(const float2*)&Y[m + n0] : make_float2(0.f, 0.f);
            ull vd0 = pack2(v.x, v.x), vd1 = pack2(v.y, v.y);
            const ulonglong2* w2 = (const ulonglong2*)&swg[(32 + e * 32 + c) * 32];
#pragma unroll
            for (int q = 0; q < 8; q++) {
                ulonglong2 w = w2[q];
                acc0[q * 2 + 0] = fma2(vd0, w.x, acc0[q * 2 + 0]);
                acc0[q * 2 + 1] = fma2(vd0, w.y, acc0[q * 2 + 1]);
                acc1[q * 2 + 0] = fma2(vd1, w.x, acc1[q * 2 + 0]);
                acc1[q * 2 + 1] = fma2(vd1, w.y, acc1[q * 2 + 1]);
            }
        }
    }
    float f0[32], f1[32];
#pragma unroll
    for (int q = 0; q < 16; q++) {
        unpack2(acc0[q], f0[q * 2], f0[q * 2 + 1]);
        unpack2(acc1[q], f1[q * 2], f1[q * 2 + 1]);
    }
    if (active) {
#pragma unroll
        for (int o = 0; o < 32; o++) {
            size_t rbase = ((size_t)(b * 32 + o) * Tin + t + dd) * NNODE;
            size_t wbase = ((size_t)(b * 32 + o) * Tout + t) * NNODE;
            float2 rv = *(const float2*)&Xc[rbase + n0];
            f0[o] += rv.x * sA[o] + sB[o];
            f1[o] += rv.y * sA[o] + sB[o];
            *(float2*)&Xn[wbase + n0] = make_float2(f0[o], f1[o]);
        }
    }
    int lane = tid & 31, warp = tid >> 5;
#pragma unroll
    for (int o = 0; o < 32; o++) {
        float s = active ? (f0[o] + f1[o]) : 0.f;
        float q = active ? (f0[o] * f0[o] + f1[o] * f1[o]) : 0.f;
#pragma unroll
        for (int off = 16; off; off >>= 1) {
            s += __shfl_down_sync(0xffffffffu, s, off);
            q += __shfl_down_sync(0xffffffffu, q, off);
        }
        if (lane == 0) { sredS[warp][o] = s; sredQ[warp][o] = q; }
    }
    __syncthreads();
    if (tid < 64) {
        int o = tid & 31;
        bool isq = (tid >= 32);
        float v = 0.f;
#pragma unroll
        for (int w = 0; w < 4; w++) v += (isq ? sredQ[w][o] : sredS[w][o]);
        size_t bidx = (size_t)(blockIdx.z * gridDim.y + blockIdx.y) * gridDim.x + blockIdx.x;
        part[bidx * 64 + tid] = v;
    }
}

// reduce partials -> fused BN scale/shift into per-layer slot
__global__ void k_redstats(const float* __restrict__ part, int nblk, float cnt,
                           const float* __restrict__ g, const float* __restrict__ bta,
                           float* __restrict__ ab) {
    int c = blockIdx.x;
    int tid = threadIdx.x;
    double s = 0.0, q = 0.0;
    for (int i = tid; i < nblk; i += 256) {
        s += (double)part[(size_t)i * 64 + c];
        q += (double)part[(size_t)i * 64 + 32 + c];
    }
    __shared__ double rs[256], rq[256];
    rs[tid] = s; rq[tid] = q;
    __syncthreads();
    for (int st = 128; st > 0; st >>= 1) {
        if (tid < st) { rs[tid] += rs[tid + st]; rq[tid] += rq[tid + st]; }
        __syncthreads();
    }
    if (tid == 0) {
        float mean = (float)(rs[0] / cnt);
        float var = (float)(rq[0] / cnt) - mean * mean;
        float a = g[c] * rsqrtf(var + BN_EPS);
        ab[c] = a;
        ab[32 + c] = bta[c] - mean * a;
    }
}

// ---------------- output head ----------------
__global__ void k_transpose_skip(const float* __restrict__ skip, const float* __restrict__ skp_b,
                                 float* __restrict__ Srelu) {
    __shared__ float tile[32][33];
    int b = blockIdx.z;
    int n0 = blockIdx.x * 32, c0 = blockIdx.y * 32;
    int n = n0 + threadIdx.x, c = c0 + threadIdx.y;
    tile[threadIdx.y][threadIdx.x] = (n < NNODE) ? skip[(size_t)(b * NSKIPC + c) * NNODE + n] : 0.f;
    __syncthreads();
    int n2 = n0 + threadIdx.y, c2 = c0 + threadIdx.x;
    float bsum = 0.f;
#pragma unroll
    for (int l = 0; l < LL; l++) bsum += skp_b[l * 256 + c2];
    if (n2 < NNODE)
        Srelu[(size_t)(b * NNODE + n2) * NSKIPC + c2] = fmaxf(tile[threadIdx.x][threadIdx.y] + bsum, 0.f);
}

__global__ void k_headfinal(const float* __restrict__ H, const float* __restrict__ o1b,
                            const float* __restrict__ o2w, const float* __restrict__ o2b,
                            float* __restrict__ out) {
    int warp = threadIdx.x >> 5, lane = threadIdx.x & 31;
    int row = blockIdx.x * 4 + warp;
    if (row >= BB * NNODE) return;
    int b = row / NNODE, n = row % NNODE;
    const float* Hr = H + (size_t)row * NENDC;
    float h[16];
#pragma unroll
    for (int i = 0; i < 16; i++)
        h[i] = fmaxf(Hr[lane + i * 32] + o1b[lane + i * 32], 0.f);
#pragma unroll
    for (int p = 0; p < NPREDC; p++) {
        float acc = 0.f;
#pragma unroll
        for (int i = 0; i < 16; i++) acc += o2w[p * NENDC + lane + i * 32] * h[i];
#pragma unroll
        for (int off = 16; off; off >>= 1) acc += __shfl_down_sync(0xffffffffu, acc, off);
        if (lane == 0) out[(size_t)(b * NPREDC + p) * NNODE + n] = acc + o2b[p];
    }
}

// ---------------- host launcher ----------------
extern "C" void kernel_launch(void* const* d_in, const int* in_sizes, int n_in,
                              void* d_out, int out_size) {
    const float* inputs = (const float*)d_in[0];
    const float* factor = (const float*)d_in[1];
    const float* map_w  = (const float*)d_in[2];
    const float* map_b  = (const float*)d_in[3];
    const float* a1w    = (const float*)d_in[4];
    const float* a1b    = (const float*)d_in[5];
    const float* a2w    = (const float*)d_in[6];
    const float* a2b    = (const float*)d_in[7];
    const float* a3w    = (const float*)d_in[8];
    const float* a3b    = (const float*)d_in[9];
    const float* enter_w = (const float*)d_in[10];
    const float* enter_b = (const float*)d_in[11];
    const float* filt_w = (const float*)d_in[12];
    const float* filt_b = (const float*)d_in[13];
    const float* gate_w = (const float*)d_in[14];
    const float* gate_b = (const float*)d_in[15];
    const float* skp_w  = (const float*)d_in[16];
    const float* skp_b  = (const float*)d_in[17];
    const float* gc_w   = (const float*)d_in[18];
    const float* gc_b   = (const float*)d_in[19];
    const float* bn_g   = (const float*)d_in[20];
    const float* bn_b   = (const float*)d_in[21];
    const float* o1w    = (const float*)d_in[22];
    const float* o1b    = (const float*)d_in[23];
    const float* o2w    = (const float*)d_in[24];
    const float* o2b    = (const float*)d_in[25];

    float *pScat, *pY, *pX0, *pX1, *pXG, *pXGcat, *pWcat, *pSkip, *pSrelu, *pO1T, *pPart, *pAB;
    cudaGetSymbolAddress((void**)&pScat, g_Scat);
    cudaGetSymbolAddress((void**)&pY, g_Y);
    cudaGetSymbolAddress((void**)&pX0, g_X0);
    cudaGetSymbolAddress((void**)&pX1, g_X1);
    cudaGetSymbolAddress((void**)&pXG, g_XG);
    cudaGetSymbolAddress((void**)&pXGcat, g_XGcat);
    cudaGetSymbolAddress((void**)&pWcat, g_Wcat);
    cudaGetSymbolAddress((void**)&pSkip, g_skip);
    cudaGetSymbolAddress((void**)&pSrelu, g_Srelu);
    cudaGetSymbolAddress((void**)&pO1T, g_o1wT);
    cudaGetSymbolAddress((void**)&pPart, g_part);
    cudaGetSymbolAddress((void**)&pAB, g_bnab);

    float* out = (float*)d_out;
    const int ySize = BB * NPREDC * NNODE;
    const int supSize = 2 * NNODE * NNODE;
    int writeSup = (out_size >= ySize + supSize) ? 1 : 0;
    float* outSup = out + ySize;

    static const int Tin[LL] = {13, 12, 10, 9, 7, 6, 4, 3};
    static const int Dd[LL]  = {1, 2, 1, 2, 1, 2, 1, 2};
    static const int To[LL]  = {12, 10, 9, 7, 6, 4, 3, 1};

    // input split + enter + prep, then layer-0 gatefilter (4th launch -> ncu capture)
    k_tmp<<<dim3(TT, BB), 256>>>(inputs, factor);
    k_enter<<<dim3(4, RFh, BB), 128>>>(inputs, factor, enter_w, enter_b, pX0);
    k_prep<<<512, 256>>>(skp_w, o1w);
    k_gatefilter<<<dim3(4, To[0], BB), 128>>>(pX0, pXG, pXGcat,
        filt_w, filt_b, gate_w, gate_b, pAB + LL * 64, Tin[0], To[0], Dd[0], 0);
    // adaptive adjacency
    k_pq<<<NNODE, 64>>>(factor, map_w, map_b, a1w, a1b);
    k_adjmlp<<<NNODE, 128>>>(a2w, a2b, a3w, a3b);
    k_softmax<<<2 * NNODE, 256>>>(outSup, writeSup);
    tgemm<<<dim3(4, 4, 2), 256>>>(pScat, pScat, pScat + 500, 500, 500, 500, 2000, 2000, 2000,
                                  1000, 1000, 1000);

    float* Xc = pX0;
    float* Xn = pX1;
    for (int i = 0; i < LL - 1; i++) {
        int slotPrev = (i == 0) ? LL : (i - 1);
        int M = BB * 32 * To[i];
        tgemm<<<dim3(16, M / 128), 256>>>(pXG, pScat, pY, M, 2000, 500,
                                          500, 2000, 2000, 0, 0, 0);
        k_gcres<<<dim3(2, To[i], BB), 128>>>(pXG, pY, Xc, Xn,
            gc_w + i * 5120, gc_b + i * 32, pAB + slotPrev * 64, pPart,
            Tin[i], To[i], Dd[i]);
        int nblk = 2 * To[i] * BB;
        k_redstats<<<32, 256>>>(pPart, nblk, (float)(BB * To[i] * NNODE),
                                bn_g + i * 32, bn_b + i * 32, pAB + i * 64);
        int j = i + 1;
        k_gatefilter<<<dim3(4, To[j], BB), 128>>>(Xn, pXG, pXGcat,
            filt_w + j * 2048, filt_b + j * 32, gate_w + j * 2048, gate_b + j * 32,
            pAB + i * 64, Tin[j], To[j], Dd[j], j);
        float* t = Xc; Xc = Xn; Xn = t;
    }
    // skip = Wcat @ XGcat  (batched over b)
    tgemm<<<dim3(4, 2, BB), 256>>>(pWcat, pXGcat, pSkip, 256, NNODE, 256,
                                   256, NNODE, NNODE, 0, 256 * NNODE, 256 * NNODE);
    // output head
    k_transpose_skip<<<dim3(16, 8, BB), dim3(32, 32)>>>(pSkip, skp_b, pSrelu);
    tgemm<<<dim3(4, 125), 256>>>(pSrelu, pO1T, pY, BB * NNODE, NENDC, NSKIPC,
                                 NSKIPC, NENDC, NENDC, 0, 0, 0);
    k_headfinal<<<(BB * NNODE + 3) / 4, 128>>>(pY, o1b, o2w, o2b, out);
}